// round 3
// baseline (speedup 1.0000x reference)
#include <cuda_runtime.h>
#include <cstdint>

// LJ constants (sigma = 1, epsilon = 1, cutoff = 5)
// SHIFT = 4*((1/5)^12 - (1/5)^6)
static __device__ __constant__ float c_shift = 4.0f * (float)(4.096e-09 - 6.4e-05);

__device__ __forceinline__ float lj_half_energy(float x, float y, float z) {
    float r2 = fmaf(x, x, fmaf(y, y, z * z));
    float inv = __fdividef(1.0f, r2);   // (sigma/r)^2, sigma = 1 (MUFU-based, ~2ulp)
    float sr6 = inv * inv * inv;        // (sigma/r)^6
    // e = 4*(sr12 - sr6) - shift ; return e/2
    float e = fmaf(4.0f, fmaf(sr6, sr6, -sr6), -c_shift);
    return 0.5f * e;
}

// Main kernel: 8 edges per thread.
// Distances: 6 x float4 (fully coalesced). Indices: int32 (2 x int4) or
// int64 (4 x longlong2) selected by a per-CTA runtime dtype probe.
__global__ void __launch_bounds__(256) lj8_kernel(
    const float4* __restrict__ d4,
    const void* __restrict__ fa,
    const void* __restrict__ sa,
    float* __restrict__ out,
    int n_oct)
{
    __shared__ int s_idx64;
    if (threadIdx.x == 0) {
        // int64-little-endian with values < 2^31 -> all odd 32-bit words zero.
        // int32 indices in [0, 100000): odd words are actual indices,
        // all-zero probability ~(1e-5)^8 -> negligible.
        const unsigned int* p = (const unsigned int*)fa;
        unsigned int acc = 0;
#pragma unroll
        for (int k = 0; k < 8; k++) acc |= p[2 * k + 1];
        s_idx64 = (acc == 0) ? 1 : 0;
    }
    __syncthreads();

    int i = blockIdx.x * blockDim.x + threadIdx.x;
    if (i >= n_oct) return;

    // 8 edges = 24 floats = 6 x float4
    float4 v[6];
#pragma unroll
    for (int k = 0; k < 6; k++) v[k] = d4[6 * (size_t)i + k];

    float h[8];
    h[0] = lj_half_energy(v[0].x, v[0].y, v[0].z);
    h[1] = lj_half_energy(v[0].w, v[1].x, v[1].y);
    h[2] = lj_half_energy(v[1].z, v[1].w, v[2].x);
    h[3] = lj_half_energy(v[2].y, v[2].z, v[2].w);
    h[4] = lj_half_energy(v[3].x, v[3].y, v[3].z);
    h[5] = lj_half_energy(v[3].w, v[4].x, v[4].y);
    h[6] = lj_half_energy(v[4].z, v[4].w, v[5].x);
    h[7] = lj_half_energy(v[5].y, v[5].z, v[5].w);

    if (!s_idx64) {
        const int4* f4 = (const int4*)fa + 2 * (size_t)i;
        const int4* s4 = (const int4*)sa + 2 * (size_t)i;
        int4 f0 = f4[0], f1 = f4[1];
        int4 s0 = s4[0], s1 = s4[1];
        atomicAdd(out + f0.x, h[0]); atomicAdd(out + s0.x, h[0]);
        atomicAdd(out + f0.y, h[1]); atomicAdd(out + s0.y, h[1]);
        atomicAdd(out + f0.z, h[2]); atomicAdd(out + s0.z, h[2]);
        atomicAdd(out + f0.w, h[3]); atomicAdd(out + s0.w, h[3]);
        atomicAdd(out + f1.x, h[4]); atomicAdd(out + s1.x, h[4]);
        atomicAdd(out + f1.y, h[5]); atomicAdd(out + s1.y, h[5]);
        atomicAdd(out + f1.z, h[6]); atomicAdd(out + s1.z, h[6]);
        atomicAdd(out + f1.w, h[7]); atomicAdd(out + s1.w, h[7]);
    } else {
        const longlong2* f2 = (const longlong2*)fa + 4 * (size_t)i;
        const longlong2* s2 = (const longlong2*)sa + 4 * (size_t)i;
#pragma unroll
        for (int k = 0; k < 4; k++) {
            longlong2 f = f2[k];
            longlong2 s = s2[k];
            atomicAdd(out + f.x, h[2 * k + 0]); atomicAdd(out + s.x, h[2 * k + 0]);
            atomicAdd(out + f.y, h[2 * k + 1]); atomicAdd(out + s.y, h[2 * k + 1]);
        }
    }
}

// Scalar tail for n_edges not divisible by 8 (not expected for 6.4M, but safe).
__global__ void lj_tail_kernel(
    const float* __restrict__ dist,
    const void* __restrict__ fa,
    const void* __restrict__ sa,
    float* __restrict__ out,
    int start, int n_edges)
{
    __shared__ int s_idx64;
    if (threadIdx.x == 0) {
        const unsigned int* p = (const unsigned int*)fa;
        unsigned int acc = 0;
#pragma unroll
        for (int k = 0; k < 8; k++) acc |= p[2 * k + 1];
        s_idx64 = (acc == 0) ? 1 : 0;
    }
    __syncthreads();

    int e = start + blockIdx.x * blockDim.x + threadIdx.x;
    if (e >= n_edges) return;
    float x = dist[3 * (size_t)e + 0];
    float y = dist[3 * (size_t)e + 1];
    float z = dist[3 * (size_t)e + 2];
    float h = lj_half_energy(x, y, z);
    long long i0, i1;
    if (s_idx64) {
        i0 = ((const long long*)fa)[e];
        i1 = ((const long long*)sa)[e];
    } else {
        i0 = ((const int*)fa)[e];
        i1 = ((const int*)sa)[e];
    }
    atomicAdd(out + i0, h);
    atomicAdd(out + i1, h);
}

extern "C" void kernel_launch(void* const* d_in, const int* in_sizes, int n_in,
                              void* d_out, int out_size)
{
    const float* dist = (const float*)d_in[0];
    const void*  fa   = d_in[1];
    const void*  sa   = d_in[2];
    float* out = (float*)d_out;

    int n_edges = in_sizes[1];  // element count of first_atom

    // Zero per-atom accumulators (d_out is poisoned before timing).
    cudaMemsetAsync(d_out, 0, (size_t)out_size * sizeof(float));

    int octs = n_edges / 8;
    if (octs > 0) {
        int threads = 256;
        int blocks = (octs + threads - 1) / threads;
        lj8_kernel<<<blocks, threads>>>((const float4*)dist, fa, sa, out, octs);
    }
    int rem_start = octs * 8;
    if (rem_start < n_edges) {
        int rem = n_edges - rem_start;
        lj_tail_kernel<<<(rem + 255) / 256, 256>>>(dist, fa, sa, out, rem_start, n_edges);
    }
}